// round 16
// baseline (speedup 1.0000x reference)
#include <cuda_runtime.h>
#include <cuda_bf16.h>
#include <math.h>
#include <stdint.h>

#define N_NODES 8192
#define H 256
#define NF 256
#define R_MIX 0.3f
#define C_SIM 0.8f
#define LOG2F_ 0.69314718055994530942f
#define MAXM 64

// ---------------- scratch (static device globals) ----------------
__device__ uint16_t g_tsh[ 8192 * 256], g_tsl[ 8192 * 256];   // layer-1 out (bf16 hi/lo)
__device__ uint16_t g_tvh[24576 * 256], g_tvl[24576 * 256];
__device__ uint16_t g_sih[ 8192 * 256], g_sil[ 8192 * 256];   // layer-2 out, SORTED rows
__device__ uint16_t g_vih[24576 * 256], g_vil[24576 * 256];   // layer-2 out, SORTED (pos*3+d)
__device__ uint16_t g_wh[4][65536];
__device__ uint16_t g_wl[4][65536];
__device__ int   g_counts [NF];
__device__ int   g_offsets[NF + 1];
__device__ int   g_nodes  [N_NODES];
__device__ int   g_pos    [N_NODES];   // node -> sorted slot (inverse of g_nodes)
__device__ float g_svar[NF], g_vvar[NF], g_ssim[NF], g_dir[NF];
__device__ int   g_done;

__device__ __forceinline__ float sspf(float x) {
    float ax = fabsf(x);
    return fmaxf(x, 0.f) + log1pf(__expf(-ax)) - LOG2F_;
}
__device__ __forceinline__ uint32_t pk2(float a, float b) {
    __nv_bfloat162 t = __floats2bfloat162_rn(a, b);
    return *reinterpret_cast<uint32_t*>(&t);
}
__device__ __forceinline__ float bres(float x) {
    __nv_bfloat16 h = __float2bfloat16(x);
    return x - __bfloat162float(h);
}
__device__ __forceinline__ float b2f(uint16_t u) {
    __nv_bfloat16 h = *reinterpret_cast<__nv_bfloat16*>(&u);
    return __bfloat162float(h);
}

// ---------------- mma/ldmatrix/cp.async wrappers (sm_103-safe) ----------------
__device__ __forceinline__ void ldsm4(uint32_t addr, uint32_t* r) {
    asm volatile("ldmatrix.sync.aligned.m8n8.x4.shared.b16 {%0,%1,%2,%3}, [%4];"
                 : "=r"(r[0]), "=r"(r[1]), "=r"(r[2]), "=r"(r[3]) : "r"(addr));
}
__device__ __forceinline__ void ldsm4t(uint32_t addr, uint32_t* r) {
    asm volatile("ldmatrix.sync.aligned.m8n8.x4.trans.shared.b16 {%0,%1,%2,%3}, [%4];"
                 : "=r"(r[0]), "=r"(r[1]), "=r"(r[2]), "=r"(r[3]) : "r"(addr));
}
__device__ __forceinline__ void mma16816(float* c, const uint32_t* a, uint32_t b0, uint32_t b1) {
    asm volatile(
        "mma.sync.aligned.m16n8k16.row.col.f32.bf16.bf16.f32 "
        "{%0,%1,%2,%3},{%4,%5,%6,%7},{%8,%9},{%0,%1,%2,%3};"
        : "+f"(c[0]), "+f"(c[1]), "+f"(c[2]), "+f"(c[3])
        : "r"(a[0]), "r"(a[1]), "r"(a[2]), "r"(a[3]), "r"(b0), "r"(b1));
}
__device__ __forceinline__ void cpa16(uint32_t dst, const void* src) {
    asm volatile("cp.async.cg.shared.global [%0], [%1], 16;" :: "r"(dst), "l"(src) : "memory");
}
__device__ __forceinline__ void cpa16z(uint32_t dst, const void* src, int sz) {
    asm volatile("cp.async.cg.shared.global [%0], [%1], 16, %2;"
                 :: "r"(dst), "l"(src), "r"(sz) : "memory");
}
__device__ __forceinline__ void cpa_commit() {
    asm volatile("cp.async.commit_group;" ::: "memory");
}
__device__ __forceinline__ void cpa_wait0() {
    asm volatile("cp.async.wait_group 0;" ::: "memory");
}

// ---------------- fused setup: block 0 = counting sort, blocks 1..256 = prepw ------
__global__ void k_setup(const int* __restrict__ frag,
                        const float* __restrict__ W1, const float* __restrict__ W2,
                        const float* __restrict__ V1, const float* __restrict__ V2)
{
    if (blockIdx.x == 0) {
        __shared__ int s_sc[8 * 256];
        __shared__ int s_off[256];
        __shared__ int s_tmp[256];
        int t = threadIdx.x, w = t >> 5, l = t & 31;

        for (int j = t; j < 2048; j += 256) s_sc[j] = 0;
        __syncthreads();

        int fv[32], lp[32];
#pragma unroll
        for (int c = 0; c < 32; c++) fv[c] = frag[(w * 32 + c) * 32 + l];
        for (int c = 0; c < 32; c++) {
            int f = fv[c];
            bool ok = (f >= 0 && f < NF);
            unsigned mask = __match_any_sync(0xffffffffu, f);
            int rank = __popc(mask & ((1u << l) - 1u));
            int before = ok ? s_sc[w * 256 + f] : 0;
            lp[c] = before + rank;
            __syncwarp();
            if (ok && rank == 0) s_sc[w * 256 + f] = before + __popc(mask);
            __syncwarp();
        }
        __syncthreads();

        {
            int run = 0;
#pragma unroll
            for (int w2 = 0; w2 < 8; w2++) {
                int v = s_sc[w2 * 256 + t];
                s_sc[w2 * 256 + t] = run;
                run += v;
            }
            g_counts[t] = run;
            s_tmp[t] = run;
            __syncthreads();
            for (int d = 1; d < 256; d <<= 1) {
                int u = (t >= d) ? s_tmp[t - d] : 0;
                __syncthreads();
                s_tmp[t] += u;
                __syncthreads();
            }
            s_off[t] = s_tmp[t] - run;
            g_offsets[t] = s_off[t];
            if (t == 255) g_offsets[256] = s_tmp[255];
        }
        __syncthreads();

        // scatter + inverse permutation (all fragment_ids are in [0,NF); a
        // hypothetical invalid id would leave its g_pos entry stale)
        for (int c = 0; c < 32; c++) {
            int f = fv[c];
            int node = (w * 32 + c) * 32 + l;
            if (f >= 0 && f < NF) {
                int pos = s_off[f] + s_sc[w * 256 + f] + lp[c];
                if (pos >= 0 && pos < N_NODES) {
                    g_nodes[pos] = node;
                    g_pos[node] = pos;
                }
            }
        }
    } else {
        int bb = blockIdx.x - 1;
        int m = bb >> 6;
        const float* src = (m == 0) ? W1 : (m == 1) ? W2 : (m == 2) ? V1 : V2;
        int i0 = ((bb & 63) * 256 + threadIdx.x) * 4;
        float4 v = *(const float4*)(src + i0);
        uint16_t* oh = g_wh[m];
        uint16_t* ol = g_wl[m];
        *(uint32_t*)&oh[i0]     = pk2(v.x, v.y);
        *(uint32_t*)&oh[i0 + 2] = pk2(v.z, v.w);
        *(uint32_t*)&ol[i0]     = pk2(bres(v.x), bres(v.y));
        *(uint32_t*)&ol[i0 + 2] = pk2(bres(v.z), bres(v.w));
    }
}

// ------------- shared GEMM pieces (proven) -------------
#define AROW 24
#define BROW 136
#define A_HL (128 * AROW)
#define B_HL (16 * BROW)
#define A_PLANE_B (A_HL * 2)
#define B_PLANE_B (B_HL * 2)
#define ABUF_B (2 * A_PLANE_B)
#define BBUF_B (2 * B_PLANE_B)
#define G_SMEM (4 * ABUF_B + 4 * BBUF_B)
#define NSCALAR_BLOCKS 64

__device__ __forceinline__ void mma_chunk(uint32_t aOff, uint32_t bOff, float acc[4][4][4]) {
    uint32_t ah[4][4], bh[2][4], tmp[2][4], al4[4];
#pragma unroll
    for (int mt = 0; mt < 4; mt++) ldsm4(aOff + mt * (16 * AROW * 2), ah[mt]);
#pragma unroll
    for (int st = 0; st < 2; st++) ldsm4t(bOff + st * 32, bh[st]);
#pragma unroll
    for (int mt = 0; mt < 4; mt++)
#pragma unroll
        for (int nt = 0; nt < 4; nt++)
            mma16816(acc[mt][nt], ah[mt], bh[nt >> 1][(nt & 1) * 2],
                     bh[nt >> 1][(nt & 1) * 2 + 1]);
#pragma unroll
    for (int st = 0; st < 2; st++) ldsm4t(bOff + B_PLANE_B + st * 32, tmp[st]);
#pragma unroll
    for (int mt = 0; mt < 4; mt++)
#pragma unroll
        for (int nt = 0; nt < 4; nt++)
            mma16816(acc[mt][nt], ah[mt], tmp[nt >> 1][(nt & 1) * 2],
                     tmp[nt >> 1][(nt & 1) * 2 + 1]);
#pragma unroll
    for (int mt = 0; mt < 4; mt++) {
        ldsm4(aOff + A_PLANE_B + mt * (16 * AROW * 2), al4);
#pragma unroll
        for (int nt = 0; nt < 4; nt++)
            mma16816(acc[mt][nt], al4, bh[nt >> 1][(nt & 1) * 2],
                     bh[nt >> 1][(nt & 1) * 2 + 1]);
    }
}

__device__ __forceinline__ void gloadA(const float* __restrict__ a1p,
                                       const float* __restrict__ a2p,
                                       int k0, float4& x, float4& y) {
    x = *(const float4*)(a1p + k0);
    y = *(const float4*)(a1p + k0 + 4);
    float4 u = *(const float4*)(a2p + k0);
    float4 v = *(const float4*)(a2p + k0 + 4);
    const float w = 1.f - R_MIX;
    x.x = fmaf(x.x, R_MIX, u.x * w); x.y = fmaf(x.y, R_MIX, u.y * w);
    x.z = fmaf(x.z, R_MIX, u.z * w); x.w = fmaf(x.w, R_MIX, u.w * w);
    y.x = fmaf(y.x, R_MIX, v.x * w); y.y = fmaf(y.y, R_MIX, v.y * w);
    y.z = fmaf(y.z, R_MIX, v.z * w); y.w = fmaf(y.w, R_MIX, v.w * w);
}

__device__ __forceinline__ void cvt_store8(uint16_t* hi_p, uint16_t* lo_p,
                                           const float4& x, const float4& y) {
    uint4 hv, lv;
    hv.x = pk2(x.x, x.y); hv.y = pk2(x.z, x.w);
    hv.z = pk2(y.x, y.y); hv.w = pk2(y.z, y.w);
    lv.x = pk2(bres(x.x), bres(x.y)); lv.y = pk2(bres(x.z), bres(x.w));
    lv.z = pk2(bres(y.x), bres(y.y)); lv.w = pk2(bres(y.z), bres(y.w));
    *reinterpret_cast<uint4*>(hi_p) = hv;
    *reinterpret_cast<uint4*>(lo_p) = lv;
}

// ---------------- layer-1 GEMM (unchanged) ----------------
__global__ __launch_bounds__(256, 2)
void k_gemm1(const float* __restrict__ A1s, const float* __restrict__ A2s,
             const float* __restrict__ A1v, const float* __restrict__ A2v,
             const uint16_t* __restrict__ Bhs, const uint16_t* __restrict__ Bls,
             const uint16_t* __restrict__ Bhv, const uint16_t* __restrict__ Blv,
             const float* __restrict__ biass,
             uint16_t* __restrict__ Csh, uint16_t* __restrict__ Csl,
             uint16_t* __restrict__ Cvh, uint16_t* __restrict__ Cvl)
{
    extern __shared__ __align__(16) uint16_t dsm[];
    const int tid = threadIdx.x, lane = tid & 31, wid = tid >> 5;
    const int warp_m = wid >> 2, warp_n = wid & 3;
    const bool isS = (blockIdx.y < NSCALAR_BLOCKS);
    const size_t rowBase = (size_t)(isS ? blockIdx.y : blockIdx.y - NSCALAR_BLOCKS) * 128;
    const int colBase = blockIdx.x * 128;
    const float* A1 = isS ? A1s : A1v;
    const float* A2 = isS ? A2s : A2v;
    const uint16_t* Bh = isS ? Bhs : Bhv;
    const uint16_t* Bl = isS ? Bls : Blv;
    const float* bias = isS ? biass : nullptr;
    uint16_t* Ch = isS ? Csh : Cvh;
    uint16_t* Cl = isS ? Csl : Cvl;

    const int am = tid >> 1, ak = (tid & 1) * 8;
    const int bk = tid >> 4, bn = (tid & 15) * 8;

    const float* a1p = A1 + (rowBase + am) * H + ak;
    const float* a2p = A2 + (rowBase + am) * H + ak;
    const uint16_t* bhp = Bh + (size_t)bk * H + colBase + bn;
    const uint16_t* blp = Bl + (size_t)bk * H + colBase + bn;

    uint32_t sA0 = (uint32_t)__cvta_generic_to_shared(dsm);
    uint32_t sB0 = sA0 + 4 * ABUF_B;
    uint32_t bDst = sB0 + (uint32_t)((bk * BROW + bn) * 2);
    uint16_t* aStore = dsm + (am * AROW + ak);

    const int a_row0 = warp_m * 64 + (lane & 7) + ((lane >> 3) & 1) * 8;
    const int a_kgrp = lane >> 4;
    uint32_t aBase = sA0 + (uint32_t)((a_row0 * AROW + a_kgrp * 8) * 2);
    const int b_krow = (lane & 7) + ((lane >> 3) & 1) * 8;
    const int b_ngrp = lane >> 4;
    uint32_t bBase = sB0 + (uint32_t)((b_krow * BROW + warp_n * 32 + b_ngrp * 8) * 2);

    float acc[4][4][4];
#pragma unroll
    for (int i = 0; i < 4; i++)
#pragma unroll
        for (int j = 0; j < 4; j++)
#pragma unroll
            for (int q = 0; q < 4; q++) acc[i][j][q] = 0.f;

    cpa16(bDst, bhp);
    cpa16(bDst + B_PLANE_B, blp);
    cpa16(bDst + BBUF_B, bhp + (size_t)16 * H);
    cpa16(bDst + BBUF_B + B_PLANE_B, blp + (size_t)16 * H);
    cpa_commit();
    {
        float4 ax, ay;
        gloadA(a1p, a2p, 0, ax, ay);
        cvt_store8(aStore, aStore + A_HL, ax, ay);
        gloadA(a1p, a2p, 16, ax, ay);
        cvt_store8(aStore + ABUF_B / 2, aStore + ABUF_B / 2 + A_HL, ax, ay);
    }
    cpa_wait0();
    __syncthreads();

    const int NT = H / 16;
    for (int t = 0; t < NT; t += 2) {
        if (t + 2 < NT) {
            int c2 = t + 2, c3 = t + 3;
            size_t k2 = (size_t)c2 * 16, k3 = (size_t)c3 * 16;
            uint32_t bd2 = bDst + (uint32_t)((c2 & 3) * BBUF_B);
            uint32_t bd3 = bDst + (uint32_t)((c3 & 3) * BBUF_B);
            cpa16(bd2, bhp + k2 * H);
            cpa16(bd2 + B_PLANE_B, blp + k2 * H);
            cpa16(bd3, bhp + k3 * H);
            cpa16(bd3 + B_PLANE_B, blp + k3 * H);
            cpa_commit();
            float4 ax, ay;
            gloadA(a1p, a2p, (int)k2, ax, ay);
            cvt_store8(aStore + (c2 & 3) * (ABUF_B / 2),
                       aStore + (c2 & 3) * (ABUF_B / 2) + A_HL, ax, ay);
            gloadA(a1p, a2p, (int)k3, ax, ay);
            cvt_store8(aStore + (c3 & 3) * (ABUF_B / 2),
                       aStore + (c3 & 3) * (ABUF_B / 2) + A_HL, ax, ay);
        }
        mma_chunk(aBase + (uint32_t)((t & 3) * ABUF_B),
                  bBase + (uint32_t)((t & 3) * BBUF_B), acc);
        mma_chunk(aBase + (uint32_t)(((t + 1) & 3) * ABUF_B),
                  bBase + (uint32_t)(((t + 1) & 3) * BBUF_B), acc);
        if (t + 2 < NT) {
            cpa_wait0();
            __syncthreads();
        }
    }

#pragma unroll
    for (int mt = 0; mt < 4; mt++) {
        size_t r0 = rowBase + warp_m * 64 + mt * 16 + (lane >> 2);
#pragma unroll
        for (int nt = 0; nt < 4; nt++) {
            int col = colBase + warp_n * 32 + nt * 8 + (lane & 3) * 2;
            float v0 = acc[mt][nt][0], v1 = acc[mt][nt][1];
            float v2 = acc[mt][nt][2], v3 = acc[mt][nt][3];
            if (bias) {
                float2 bb = *(const float2*)&bias[col];
                v0 += bb.x; v1 += bb.y; v2 += bb.x; v3 += bb.y;
            }
            v0 = sspf(v0); v1 = sspf(v1); v2 = sspf(v2); v3 = sspf(v3);
            *(uint32_t*)&Ch[r0 * H + col]       = pk2(v0, v1);
            *(uint32_t*)&Cl[r0 * H + col]       = pk2(bres(v0), bres(v1));
            *(uint32_t*)&Ch[(r0 + 8) * H + col] = pk2(v2, v3);
            *(uint32_t*)&Cl[(r0 + 8) * H + col] = pk2(bres(v2), bres(v3));
        }
    }
}

// -------- layer-2 GEMM: bf16 planes in -> bf16 hi/lo planes out, PERMUTED rows ----
// Output row for scalar node r = g_pos[r]; for vector flat row m: node=m/3, d=m%3,
// dst = g_pos[node]*3+d. Scattered stores (no latency exposure) buy k_frag
// perfectly contiguous reads.
__global__ __launch_bounds__(256, 2)
void k_gemm2(const uint16_t* __restrict__ Ahs, const uint16_t* __restrict__ Als,
             const uint16_t* __restrict__ Ahv, const uint16_t* __restrict__ Alv,
             const uint16_t* __restrict__ Bhs, const uint16_t* __restrict__ Bls,
             const uint16_t* __restrict__ Bhv, const uint16_t* __restrict__ Blv,
             const float* __restrict__ biass,
             uint16_t* __restrict__ Csh, uint16_t* __restrict__ Csl,
             uint16_t* __restrict__ Cvh, uint16_t* __restrict__ Cvl)
{
    extern __shared__ __align__(16) uint16_t dsm[];
    const int tid = threadIdx.x, lane = tid & 31, wid = tid >> 5;
    const int warp_m = wid >> 2, warp_n = wid & 3;
    const bool isS = (blockIdx.y < NSCALAR_BLOCKS);
    const size_t rowBase = (size_t)(isS ? blockIdx.y : blockIdx.y - NSCALAR_BLOCKS) * 128;
    const int colBase = blockIdx.x * 128;
    const uint16_t* Ah = isS ? Ahs : Ahv;
    const uint16_t* Al = isS ? Als : Alv;
    const uint16_t* Bh = isS ? Bhs : Bhv;
    const uint16_t* Bl = isS ? Bls : Blv;
    const float* bias = isS ? biass : nullptr;
    uint16_t* Ch = isS ? Csh : Cvh;
    uint16_t* Cl = isS ? Csl : Cvl;

    const int am = tid >> 1, ak = (tid & 1) * 8;
    const int bk = tid >> 4, bn = (tid & 15) * 8;

    const uint16_t* ahp = Ah + (rowBase + am) * H + ak;
    const uint16_t* alp = Al + (rowBase + am) * H + ak;
    const uint16_t* bhp = Bh + (size_t)bk * H + colBase + bn;
    const uint16_t* blp = Bl + (size_t)bk * H + colBase + bn;

    uint32_t sA0 = (uint32_t)__cvta_generic_to_shared(dsm);
    uint32_t sB0 = sA0 + 4 * ABUF_B;
    uint32_t aDst = sA0 + (uint32_t)((am * AROW + ak) * 2);
    uint32_t bDst = sB0 + (uint32_t)((bk * BROW + bn) * 2);

    const int a_row0 = warp_m * 64 + (lane & 7) + ((lane >> 3) & 1) * 8;
    const int a_kgrp = lane >> 4;
    uint32_t aBase = sA0 + (uint32_t)((a_row0 * AROW + a_kgrp * 8) * 2);
    const int b_krow = (lane & 7) + ((lane >> 3) & 1) * 8;
    const int b_ngrp = lane >> 4;
    uint32_t bBase = sB0 + (uint32_t)((b_krow * BROW + warp_n * 32 + b_ngrp * 8) * 2);

    float acc[4][4][4];
#pragma unroll
    for (int i = 0; i < 4; i++)
#pragma unroll
        for (int j = 0; j < 4; j++)
#pragma unroll
            for (int q = 0; q < 4; q++) acc[i][j][q] = 0.f;

#pragma unroll
    for (int c = 0; c < 2; c++) {
        size_t k0 = (size_t)c * 16;
        uint32_t ad = aDst + (uint32_t)(c * ABUF_B);
        uint32_t bd = bDst + (uint32_t)(c * BBUF_B);
        cpa16(ad, ahp + k0);
        cpa16(ad + A_PLANE_B, alp + k0);
        cpa16(bd, bhp + k0 * H);
        cpa16(bd + B_PLANE_B, blp + k0 * H);
    }
    cpa_commit();
    cpa_wait0();
    __syncthreads();

    const int NT = H / 16;
    for (int t = 0; t < NT; t += 2) {
        if (t + 2 < NT) {
#pragma unroll
            for (int d = 2; d < 4; d++) {
                int c = t + d;
                size_t k0 = (size_t)c * 16;
                uint32_t ad = aDst + (uint32_t)((c & 3) * ABUF_B);
                uint32_t bd = bDst + (uint32_t)((c & 3) * BBUF_B);
                cpa16(ad, ahp + k0);
                cpa16(ad + A_PLANE_B, alp + k0);
                cpa16(bd, bhp + k0 * H);
                cpa16(bd + B_PLANE_B, blp + k0 * H);
            }
            cpa_commit();
        }
        mma_chunk(aBase + (uint32_t)((t & 3) * ABUF_B),
                  bBase + (uint32_t)((t & 3) * BBUF_B), acc);
        mma_chunk(aBase + (uint32_t)(((t + 1) & 3) * ABUF_B),
                  bBase + (uint32_t)(((t + 1) & 3) * BBUF_B), acc);
        if (t + 2 < NT) {
            cpa_wait0();
            __syncthreads();
        }
    }

#pragma unroll
    for (int mt = 0; mt < 4; mt++) {
        size_t r0 = rowBase + warp_m * 64 + mt * 16 + (lane >> 2);
        size_t pr0, pr8;
        if (isS) {
            pr0 = (size_t)__ldg(&g_pos[r0]);
            pr8 = (size_t)__ldg(&g_pos[r0 + 8]);
        } else {
            int m0 = (int)r0, n0 = m0 / 3, d0 = m0 - 3 * n0;
            int m8 = m0 + 8, n8 = m8 / 3, d8 = m8 - 3 * n8;
            pr0 = (size_t)__ldg(&g_pos[n0]) * 3 + d0;
            pr8 = (size_t)__ldg(&g_pos[n8]) * 3 + d8;
        }
#pragma unroll
        for (int nt = 0; nt < 4; nt++) {
            int col = colBase + warp_n * 32 + nt * 8 + (lane & 3) * 2;
            float v0 = acc[mt][nt][0], v1 = acc[mt][nt][1];
            float v2 = acc[mt][nt][2], v3 = acc[mt][nt][3];
            if (bias) {
                float2 bb = *(const float2*)&bias[col];
                v0 += bb.x; v1 += bb.y; v2 += bb.x; v3 += bb.y;
            }
            *(uint32_t*)&Ch[pr0 * H + col] = pk2(v0, v1);
            *(uint32_t*)&Cl[pr0 * H + col] = pk2(bres(v0), bres(v1));
            *(uint32_t*)&Ch[pr8 * H + col] = pk2(v2, v3);
            *(uint32_t*)&Cl[pr8 * H + col] = pk2(bres(v2), bres(v3));
        }
    }
}

// ---------------- per-fragment stats: contiguous-stream Gram pipeline --------------
// Layer-2 outputs are fragment-sorted, so each block streams rows [off, off+cnt)
// with zero indirection. 2-buffer 16-unit flat pipeline, lookahead 2.
#define ZROW 72
#define ZPLANE (64 * ZROW)
#define FRAG_SMEM (2 * 2 * ZPLANE * 2)   // 36864 bytes

__global__ __launch_bounds__(256, 2)
void k_frag(float* __restrict__ out) {
    extern __shared__ __align__(16) uint16_t z[];
    __shared__ float sdiag[64];
    __shared__ float rd[48];
    __shared__ int s_last;
    int f = blockIdx.x, t = threadIdx.x;
    int cnt = g_counts[f], off = g_offsets[f];
    int wid = t >> 5, lane = t & 31;
    float serr = 0.f, derr = 0.f;
    float tr0 = 0.f, tr123 = 0.f, gs0 = 0.f, gs123 = 0.f;

    uint32_t z0 = (uint32_t)__cvta_generic_to_shared(z);

    if (cnt >= 2 && cnt <= MAXM) {
        const int Mt = (cnt + 15) >> 4;
        int tm[2] = {-1, -1}, tn[2] = {-1, -1};
        {
            int idx = 0;
            for (int mt = 0; mt < Mt; mt++)
                for (int nt = mt; nt < Mt; nt++) {
                    if ((idx & 7) == wid) {
                        int s = idx >> 3;
                        if (s < 2) { tm[s] = mt; tn[s] = nt; }
                    }
                    idx++;
                }
        }
        const int lrow = t >> 2;
        const int lkq = (t & 3) * 16;
        const bool have = (lrow < cnt);
        const size_t srow = (size_t)(off + (have ? lrow : 0));
        const int fr = (lane & 7) + ((lane >> 3) & 1) * 8;
        const int fk = (lane >> 4) * 8;
        const int sz = have ? 16 : 0;

        // issue one 64x64 chunk unit u (feat = u>>2, kc = u&3) into buffer u&1
        auto issue_unit = [&](int u) {
            int feat = u >> 2, kc = u & 3;
            const uint16_t *sh, *slo;
            if (feat == 0) {
                sh = g_sih + srow * H; slo = g_sil + srow * H;
            } else {
                sh  = g_vih + (srow * 3 + feat - 1) * H;
                slo = g_vil + (srow * 3 + feat - 1) * H;
            }
            uint32_t dst = z0 + (uint32_t)(((u & 1) * 2 * ZPLANE + lrow * ZROW + lkq) * 2);
            cpa16z(dst, sh + kc * 64 + lkq, sz);
            cpa16z(dst + 16, sh + kc * 64 + lkq + 8, sz);
            cpa16z(dst + ZPLANE * 2, slo + kc * 64 + lkq, sz);
            cpa16z(dst + ZPLANE * 2 + 16, slo + kc * 64 + lkq + 8, sz);
            cpa_commit();
        };

        issue_unit(0);
        issue_unit(1);

        float acc[2][2][4];
        for (int u = 0; u < 16; u++) {
            int kc = u & 3;
            if (kc == 0) {
#pragma unroll
                for (int a = 0; a < 2; a++)
#pragma unroll
                    for (int b = 0; b < 2; b++)
#pragma unroll
                        for (int q = 0; q < 4; q++) acc[a][b][q] = 0.f;
            }
            if (u < 15) asm volatile("cp.async.wait_group 1;" ::: "memory");
            else        asm volatile("cp.async.wait_group 0;" ::: "memory");
            __syncthreads();

            uint32_t zhb = z0 + (uint32_t)((u & 1) * 2 * ZPLANE * 2);
            uint32_t zlb = zhb + (uint32_t)(ZPLANE * 2);
#pragma unroll
            for (int ti = 0; ti < 2; ti++) {
                if (tm[ti] < 0) continue;
#pragma unroll
                for (int ks = 0; ks < 4; ks++) {
                    uint32_t aoff = (uint32_t)(((tm[ti] * 16 + fr) * ZROW + ks * 16 + fk) * 2);
                    uint32_t boff = (uint32_t)(((tn[ti] * 16 + fr) * ZROW + ks * 16 + fk) * 2);
                    uint32_t ah[4], al[4], bh[4], bl[4];
                    ldsm4(zhb + aoff, ah);
                    ldsm4(zlb + aoff, al);
                    ldsm4(zhb + boff, bh);
                    ldsm4(zlb + boff, bl);
                    mma16816(acc[ti][0], ah, bh[0], bh[2]);
                    mma16816(acc[ti][1], ah, bh[1], bh[3]);
                    mma16816(acc[ti][0], ah, bl[0], bl[2]);
                    mma16816(acc[ti][1], ah, bl[1], bl[3]);
                    mma16816(acc[ti][0], al, bh[0], bh[2]);
                    mma16816(acc[ti][1], al, bh[1], bh[3]);
                }
            }
            __syncthreads();
            if (u + 2 < 16) issue_unit(u + 2);

            if (kc == 3) {
                int feat = u >> 2;
                {
                    int r = lane >> 2, c = (lane & 3) * 2;
#pragma unroll
                    for (int ti = 0; ti < 2; ti++) {
                        if (tm[ti] < 0 || tm[ti] != tn[ti]) continue;
#pragma unroll
                        for (int hh = 0; hh < 2; hh++) {
                            int nl0 = hh * 8 + c;
                            if (r == nl0)     sdiag[tm[ti] * 16 + r]     = acc[ti][hh][0];
                            if (r == nl0 + 1) sdiag[tm[ti] * 16 + r]     = acc[ti][hh][1];
                            if (r + 8 == nl0)     sdiag[tm[ti] * 16 + r + 8] = acc[ti][hh][2];
                            if (r + 8 == nl0 + 1) sdiag[tm[ti] * 16 + r + 8] = acc[ti][hh][3];
                        }
                    }
                }
                __syncthreads();

                if (t < cnt) {
                    float d = sdiag[t];
                    if (feat == 0) tr0 += d; else tr123 += d;
                }

                {
                    float err = 0.f, gsum = 0.f;
                    int r = lane >> 2, c = (lane & 3) * 2;
#pragma unroll
                    for (int ti = 0; ti < 2; ti++) {
                        if (tm[ti] < 0) continue;
                        int mb = tm[ti] * 16, nb = tn[ti] * 16;
                        bool isDiag = (tm[ti] == tn[ti]);
#pragma unroll
                        for (int hh = 0; hh < 2; hh++) {
                            int n0 = nb + hh * 8 + c;
#pragma unroll
                            for (int q = 0; q < 4; q++) {
                                int m = mb + r + (q >> 1) * 8;
                                int n = n0 + (q & 1);
                                float v = acc[ti][hh][q];
                                if (!isDiag) {
                                    gsum += 2.f * v;
                                } else {
                                    if (m < n) gsum += 2.f * v;
                                    else if (m == n) gsum += v;
                                }
                                if (n < cnt && m < n) {
                                    float rs = rsqrtf(fmaxf(sdiag[m] * sdiag[n], 1e-24f));
                                    float e = fmaf(v, rs, -C_SIM);
                                    err = fmaf(e, e, err);
                                }
                            }
                        }
                    }
                    if (feat == 0) { serr = err; gs0 = gsum; }
                    else { derr += err; gs123 += gsum; }
                }
                __syncthreads();
            }
        }
    } else if (cnt > MAXM) {
        // fallback (never expected): sorted-layout gmem-direct, exact two-pass
        float* mean = (float*)z;
        float as = 0.f, a0m = 0.f, a1m = 0.f, a2m = 0.f;
        for (int m = 0; m < cnt; m++) {
            size_t sr = (size_t)(off + m);
            as += b2f(g_sih[sr * H + t]) + b2f(g_sil[sr * H + t]);
            size_t vb = sr * 3 * H;
            a0m += b2f(g_vih[vb + t]) + b2f(g_vil[vb + t]);
            a1m += b2f(g_vih[vb + H + t]) + b2f(g_vil[vb + H + t]);
            a2m += b2f(g_vih[vb + 2 * H + t]) + b2f(g_vil[vb + 2 * H + t]);
        }
        float invn = 1.f / (float)cnt;
        mean[t] = as * invn; mean[256 + t] = a0m * invn;
        mean[512 + t] = a1m * invn; mean[768 + t] = a2m * invn;
        __syncthreads();
        for (int m = 0; m < cnt; m++) {
            size_t sr = (size_t)(off + m);
            float d0 = b2f(g_sih[sr * H + t]) + b2f(g_sil[sr * H + t]) - mean[t];
            tr0 = fmaf(d0, d0, tr0);
            size_t vb = sr * 3 * H;
            float d1 = b2f(g_vih[vb + t]) + b2f(g_vil[vb + t]) - mean[256 + t];
            float d2 = b2f(g_vih[vb + H + t]) + b2f(g_vil[vb + H + t]) - mean[512 + t];
            float d3 = b2f(g_vih[vb + 2 * H + t]) + b2f(g_vil[vb + 2 * H + t]) - mean[768 + t];
            tr123 = fmaf(d1, d1, tr123); tr123 = fmaf(d2, d2, tr123); tr123 = fmaf(d3, d3, tr123);
        }
        for (int feat = 0; feat < 4; feat++) {
            float acc = 0.f;
            for (int a = wid; a < cnt - 1; a += 8) {
                size_t sa_ = (size_t)(off + a);
                const uint16_t* rah = (feat == 0) ? g_sih + sa_ * H
                                                  : g_vih + (sa_ * 3 + feat - 1) * H;
                const uint16_t* ral = (feat == 0) ? g_sil + sa_ * H
                                                  : g_vil + (sa_ * 3 + feat - 1) * H;
                for (int b = a + 1 + lane; b < cnt; b += 32) {
                    size_t sb_ = (size_t)(off + b);
                    const uint16_t* rbh = (feat == 0) ? g_sih + sb_ * H
                                                      : g_vih + (sb_ * 3 + feat - 1) * H;
                    const uint16_t* rbl = (feat == 0) ? g_sil + sb_ * H
                                                      : g_vil + (sb_ * 3 + feat - 1) * H;
                    float dot = 0.f, sa = 0.f, sb = 0.f;
                    for (int k = 0; k < H; k++) {
                        float x = b2f(rah[k]) + b2f(ral[k]);
                        float y = b2f(rbh[k]) + b2f(rbl[k]);
                        dot = fmaf(x, y, dot);
                        sa = fmaf(x, x, sa);
                        sb = fmaf(y, y, sb);
                    }
                    float e = dot / (fmaxf(sqrtf(sa), 1e-12f) * fmaxf(sqrtf(sb), 1e-12f)) - C_SIM;
                    acc = fmaf(e, e, acc);
                }
            }
            if (feat == 0) serr = acc; else derr += acc;
        }
    }

    for (int o = 16; o; o >>= 1) {
        tr0   += __shfl_xor_sync(0xffffffffu, tr0, o);
        tr123 += __shfl_xor_sync(0xffffffffu, tr123, o);
        gs0   += __shfl_xor_sync(0xffffffffu, gs0, o);
        gs123 += __shfl_xor_sync(0xffffffffu, gs123, o);
        serr  += __shfl_xor_sync(0xffffffffu, serr, o);
        derr  += __shfl_xor_sync(0xffffffffu, derr, o);
    }
    if (lane == 0) {
        rd[wid] = tr0; rd[8 + wid] = tr123; rd[16 + wid] = gs0;
        rd[24 + wid] = gs123; rd[32 + wid] = serr; rd[40 + wid] = derr;
    }
    __syncthreads();
    if (t == 0) {
        float a = 0.f, b = 0.f, c = 0.f, d = 0.f, e = 0.f, g = 0.f;
        for (int i = 0; i < 8; i++) {
            a += rd[i]; b += rd[8 + i]; c += rd[16 + i];
            d += rd[24 + i]; e += rd[32 + i]; g += rd[40 + i];
        }
        float invn = 1.f / (float)(cnt > 0 ? cnt : 1);
        g_svar[f] = a - c * invn;
        g_vvar[f] = b - d * invn;
        g_ssim[f] = e;
        g_dir[f]  = g;
        __threadfence();
        int old = atomicAdd(&g_done, 1);
        s_last = (old == NF - 1) ? 1 : 0;
    }
    __syncthreads();

    if (s_last) {
        __threadfence();
        float n  = (float)g_counts[t];
        float pc = n * (n - 1.f) * 0.5f;
        float ns  = fmaxf(n, 1.f);
        float pcs = fmaxf(pc, 1.f);
        float sl = g_svar[t] / ns + g_ssim[t] / pcs;
        float vl = g_vvar[t] / ns + g_dir[t] / (3.f * pcs);
        float fl = 0.5f * sl + 0.5f * vl;
        float val  = (pc > 0.f) ? fl : 0.f;
        float cntv = (pc > 0.f) ? 1.f : 0.f;
        for (int o = 16; o; o >>= 1) {
            val  += __shfl_xor_sync(0xffffffffu, val, o);
            cntv += __shfl_xor_sync(0xffffffffu, cntv, o);
        }
        __syncthreads();
        if (lane == 0) { rd[wid] = val; rd[8 + wid] = cntv; }
        __syncthreads();
        if (t == 0) {
            float tot = 0.f, tc = 0.f;
            for (int i = 0; i < 8; i++) { tot += rd[i]; tc += rd[8 + i]; }
            out[0] = (tc > 0.f) ? tot / fmaxf(tc, 1.f) : 0.f;
            g_done = 0;
        }
    }
}

// ---------------- launch ----------------
extern "C" void kernel_launch(void* const* d_in, const int* in_sizes, int n_in,
                              void* d_out, int out_size)
{
    const float* ss = (const float*)d_in[0];
    const float* sl = (const float*)d_in[1];
    const float* vs = (const float*)d_in[2];
    const float* vl = (const float*)d_in[3];
    const float* W1 = (const float*)d_in[4];
    const float* b1 = (const float*)d_in[5];
    const float* W2 = (const float*)d_in[6];
    const float* b2 = (const float*)d_in[7];
    const float* V1 = (const float*)d_in[8];
    const float* V2 = (const float*)d_in[9];
    const int*   frag = (const int*)d_in[10];
    float* out = (float*)d_out;

    void *pwh, *pwl, *ptsh, *ptsl, *ptvh, *ptvl, *psih, *psil, *pvih, *pvil;
    cudaGetSymbolAddress(&pwh, g_wh);
    cudaGetSymbolAddress(&pwl, g_wl);
    cudaGetSymbolAddress(&ptsh, g_tsh);
    cudaGetSymbolAddress(&ptsl, g_tsl);
    cudaGetSymbolAddress(&ptvh, g_tvh);
    cudaGetSymbolAddress(&ptvl, g_tvl);
    cudaGetSymbolAddress(&psih, g_sih);
    cudaGetSymbolAddress(&psil, g_sil);
    cudaGetSymbolAddress(&pvih, g_vih);
    cudaGetSymbolAddress(&pvil, g_vil);
    const uint16_t* wh = (const uint16_t*)pwh;
    const uint16_t* wl = (const uint16_t*)pwl;

    k_setup<<<257, 256>>>(frag, W1, W2, V1, V2);

    cudaFuncSetAttribute(k_gemm1, cudaFuncAttributeMaxDynamicSharedMemorySize, G_SMEM);
    cudaFuncSetAttribute(k_gemm2, cudaFuncAttributeMaxDynamicSharedMemorySize, G_SMEM);
    cudaFuncSetAttribute(k_frag, cudaFuncAttributeMaxDynamicSharedMemorySize, FRAG_SMEM);

    dim3 g(2, NSCALAR_BLOCKS + 192);
    k_gemm1<<<g, 256, G_SMEM>>>(ss, sl, vs, vl,
                                wh + 0 * 65536, wl + 0 * 65536,
                                wh + 2 * 65536, wl + 2 * 65536,
                                b1,
                                (uint16_t*)ptsh, (uint16_t*)ptsl,
                                (uint16_t*)ptvh, (uint16_t*)ptvl);
    k_gemm2<<<g, 256, G_SMEM>>>((uint16_t*)ptsh, (uint16_t*)ptsl,
                                (uint16_t*)ptvh, (uint16_t*)ptvl,
                                wh + 1 * 65536, wl + 1 * 65536,
                                wh + 3 * 65536, wl + 3 * 65536,
                                b2,
                                (uint16_t*)psih, (uint16_t*)psil,
                                (uint16_t*)pvih, (uint16_t*)pvil);

    k_frag<<<NF, 256, FRAG_SMEM>>>(out);
}

// round 17
// speedup vs baseline: 1.0150x; 1.0150x over previous
#include <cuda_runtime.h>
#include <cuda_bf16.h>
#include <math.h>
#include <stdint.h>

#define N_NODES 8192
#define H 256
#define NF 256
#define R_MIX 0.3f
#define C_SIM 0.8f
#define LOG2F_ 0.69314718055994530942f
#define MAXM 64

// ---------------- scratch (static device globals) ----------------
__device__ uint16_t g_tsh[ 8192 * 256], g_tsl[ 8192 * 256];   // layer-1 out (bf16 hi/lo)
__device__ uint16_t g_tvh[24576 * 256], g_tvl[24576 * 256];
__device__ uint16_t g_sih[ 8192 * 256], g_sil[ 8192 * 256];   // layer-2 out (bf16 hi/lo)
__device__ uint16_t g_vih[24576 * 256], g_vil[24576 * 256];
__device__ uint16_t g_wh[4][65536];
__device__ uint16_t g_wl[4][65536];
__device__ int   g_counts [NF];
__device__ int   g_offsets[NF + 1];
__device__ int   g_nodes  [N_NODES];
__device__ float g_svar[NF], g_vvar[NF], g_ssim[NF], g_dir[NF];
__device__ int   g_done;

__device__ __forceinline__ float sspf(float x) {
    float ax = fabsf(x);
    return fmaxf(x, 0.f) + log1pf(__expf(-ax)) - LOG2F_;
}
__device__ __forceinline__ uint32_t pk2(float a, float b) {
    __nv_bfloat162 t = __floats2bfloat162_rn(a, b);
    return *reinterpret_cast<uint32_t*>(&t);
}
__device__ __forceinline__ float bres(float x) {
    __nv_bfloat16 h = __float2bfloat16(x);
    return x - __bfloat162float(h);
}
__device__ __forceinline__ float b2f(uint16_t u) {
    __nv_bfloat16 h = *reinterpret_cast<__nv_bfloat16*>(&u);
    return __bfloat162float(h);
}

// ---------------- mma/ldmatrix/cp.async wrappers (sm_103-safe) ----------------
__device__ __forceinline__ void ldsm4(uint32_t addr, uint32_t* r) {
    asm volatile("ldmatrix.sync.aligned.m8n8.x4.shared.b16 {%0,%1,%2,%3}, [%4];"
                 : "=r"(r[0]), "=r"(r[1]), "=r"(r[2]), "=r"(r[3]) : "r"(addr));
}
__device__ __forceinline__ void ldsm4t(uint32_t addr, uint32_t* r) {
    asm volatile("ldmatrix.sync.aligned.m8n8.x4.trans.shared.b16 {%0,%1,%2,%3}, [%4];"
                 : "=r"(r[0]), "=r"(r[1]), "=r"(r[2]), "=r"(r[3]) : "r"(addr));
}
__device__ __forceinline__ void mma16816(float* c, const uint32_t* a, uint32_t b0, uint32_t b1) {
    asm volatile(
        "mma.sync.aligned.m16n8k16.row.col.f32.bf16.bf16.f32 "
        "{%0,%1,%2,%3},{%4,%5,%6,%7},{%8,%9},{%0,%1,%2,%3};"
        : "+f"(c[0]), "+f"(c[1]), "+f"(c[2]), "+f"(c[3])
        : "r"(a[0]), "r"(a[1]), "r"(a[2]), "r"(a[3]), "r"(b0), "r"(b1));
}
__device__ __forceinline__ void cpa16(uint32_t dst, const void* src) {
    asm volatile("cp.async.cg.shared.global [%0], [%1], 16;" :: "r"(dst), "l"(src) : "memory");
}
__device__ __forceinline__ void cpa16z(uint32_t dst, const void* src, int sz) {
    asm volatile("cp.async.cg.shared.global [%0], [%1], 16, %2;"
                 :: "r"(dst), "l"(src), "r"(sz) : "memory");
}
__device__ __forceinline__ void cpa_commit() {
    asm volatile("cp.async.commit_group;" ::: "memory");
}
__device__ __forceinline__ void cpa_wait0() {
    asm volatile("cp.async.wait_group 0;" ::: "memory");
}

// ---------------- fused setup: block 0 = counting sort, blocks 1..256 = prepw ------
__global__ void k_setup(const int* __restrict__ frag,
                        const float* __restrict__ W1, const float* __restrict__ W2,
                        const float* __restrict__ V1, const float* __restrict__ V2)
{
    if (blockIdx.x == 0) {
        __shared__ int s_sc[8 * 256];
        __shared__ int s_off[256];
        __shared__ int s_tmp[256];
        int t = threadIdx.x, w = t >> 5, l = t & 31;

        for (int j = t; j < 2048; j += 256) s_sc[j] = 0;
        __syncthreads();

        int fv[32], lp[32];
#pragma unroll
        for (int c = 0; c < 32; c++) fv[c] = frag[(w * 32 + c) * 32 + l];
        for (int c = 0; c < 32; c++) {
            int f = fv[c];
            bool ok = (f >= 0 && f < NF);
            unsigned mask = __match_any_sync(0xffffffffu, f);
            int rank = __popc(mask & ((1u << l) - 1u));
            int before = ok ? s_sc[w * 256 + f] : 0;
            lp[c] = before + rank;
            __syncwarp();
            if (ok && rank == 0) s_sc[w * 256 + f] = before + __popc(mask);
            __syncwarp();
        }
        __syncthreads();

        {
            int run = 0;
#pragma unroll
            for (int w2 = 0; w2 < 8; w2++) {
                int v = s_sc[w2 * 256 + t];
                s_sc[w2 * 256 + t] = run;
                run += v;
            }
            g_counts[t] = run;
            s_tmp[t] = run;
            __syncthreads();
            for (int d = 1; d < 256; d <<= 1) {
                int u = (t >= d) ? s_tmp[t - d] : 0;
                __syncthreads();
                s_tmp[t] += u;
                __syncthreads();
            }
            s_off[t] = s_tmp[t] - run;
            g_offsets[t] = s_off[t];
            if (t == 255) g_offsets[256] = s_tmp[255];
        }
        __syncthreads();

        for (int c = 0; c < 32; c++) {
            int f = fv[c];
            if (f >= 0 && f < NF) {
                int pos = s_off[f] + s_sc[w * 256 + f] + lp[c];
                if (pos >= 0 && pos < N_NODES)
                    g_nodes[pos] = (w * 32 + c) * 32 + l;
            }
        }
    } else {
        int bb = blockIdx.x - 1;
        int m = bb >> 6;
        const float* src = (m == 0) ? W1 : (m == 1) ? W2 : (m == 2) ? V1 : V2;
        int i0 = ((bb & 63) * 256 + threadIdx.x) * 4;
        float4 v = *(const float4*)(src + i0);
        uint16_t* oh = g_wh[m];
        uint16_t* ol = g_wl[m];
        *(uint32_t*)&oh[i0]     = pk2(v.x, v.y);
        *(uint32_t*)&oh[i0 + 2] = pk2(v.z, v.w);
        *(uint32_t*)&ol[i0]     = pk2(bres(v.x), bres(v.y));
        *(uint32_t*)&ol[i0 + 2] = pk2(bres(v.z), bres(v.w));
    }
}

// ------------- shared GEMM pieces (proven) -------------
#define AROW 24
#define BROW 136
#define A_HL (128 * AROW)
#define B_HL (16 * BROW)
#define A_PLANE_B (A_HL * 2)
#define B_PLANE_B (B_HL * 2)
#define ABUF_B (2 * A_PLANE_B)
#define BBUF_B (2 * B_PLANE_B)
#define G_SMEM (4 * ABUF_B + 4 * BBUF_B)
#define NSCALAR_BLOCKS 64

__device__ __forceinline__ void mma_chunk(uint32_t aOff, uint32_t bOff, float acc[4][4][4]) {
    uint32_t ah[4][4], bh[2][4], tmp[2][4], al4[4];
#pragma unroll
    for (int mt = 0; mt < 4; mt++) ldsm4(aOff + mt * (16 * AROW * 2), ah[mt]);
#pragma unroll
    for (int st = 0; st < 2; st++) ldsm4t(bOff + st * 32, bh[st]);
#pragma unroll
    for (int mt = 0; mt < 4; mt++)
#pragma unroll
        for (int nt = 0; nt < 4; nt++)
            mma16816(acc[mt][nt], ah[mt], bh[nt >> 1][(nt & 1) * 2],
                     bh[nt >> 1][(nt & 1) * 2 + 1]);
#pragma unroll
    for (int st = 0; st < 2; st++) ldsm4t(bOff + B_PLANE_B + st * 32, tmp[st]);
#pragma unroll
    for (int mt = 0; mt < 4; mt++)
#pragma unroll
        for (int nt = 0; nt < 4; nt++)
            mma16816(acc[mt][nt], ah[mt], tmp[nt >> 1][(nt & 1) * 2],
                     tmp[nt >> 1][(nt & 1) * 2 + 1]);
#pragma unroll
    for (int mt = 0; mt < 4; mt++) {
        ldsm4(aOff + A_PLANE_B + mt * (16 * AROW * 2), al4);
#pragma unroll
        for (int nt = 0; nt < 4; nt++)
            mma16816(acc[mt][nt], al4, bh[nt >> 1][(nt & 1) * 2],
                     bh[nt >> 1][(nt & 1) * 2 + 1]);
    }
}

__device__ __forceinline__ void gloadA(const float* __restrict__ a1p,
                                       const float* __restrict__ a2p,
                                       int k0, float4& x, float4& y) {
    x = *(const float4*)(a1p + k0);
    y = *(const float4*)(a1p + k0 + 4);
    float4 u = *(const float4*)(a2p + k0);
    float4 v = *(const float4*)(a2p + k0 + 4);
    const float w = 1.f - R_MIX;
    x.x = fmaf(x.x, R_MIX, u.x * w); x.y = fmaf(x.y, R_MIX, u.y * w);
    x.z = fmaf(x.z, R_MIX, u.z * w); x.w = fmaf(x.w, R_MIX, u.w * w);
    y.x = fmaf(y.x, R_MIX, v.x * w); y.y = fmaf(y.y, R_MIX, v.y * w);
    y.z = fmaf(y.z, R_MIX, v.z * w); y.w = fmaf(y.w, R_MIX, v.w * w);
}

__device__ __forceinline__ void cvt_store8(uint16_t* hi_p, uint16_t* lo_p,
                                           const float4& x, const float4& y) {
    uint4 hv, lv;
    hv.x = pk2(x.x, x.y); hv.y = pk2(x.z, x.w);
    hv.z = pk2(y.x, y.y); hv.w = pk2(y.z, y.w);
    lv.x = pk2(bres(x.x), bres(x.y)); lv.y = pk2(bres(x.z), bres(x.w));
    lv.z = pk2(bres(y.x), bres(y.y)); lv.w = pk2(bres(y.z), bres(y.w));
    *reinterpret_cast<uint4*>(hi_p) = hv;
    *reinterpret_cast<uint4*>(lo_p) = lv;
}

// ---------------- layer-1 GEMM (unchanged) ----------------
__global__ __launch_bounds__(256, 2)
void k_gemm1(const float* __restrict__ A1s, const float* __restrict__ A2s,
             const float* __restrict__ A1v, const float* __restrict__ A2v,
             const uint16_t* __restrict__ Bhs, const uint16_t* __restrict__ Bls,
             const uint16_t* __restrict__ Bhv, const uint16_t* __restrict__ Blv,
             const float* __restrict__ biass,
             uint16_t* __restrict__ Csh, uint16_t* __restrict__ Csl,
             uint16_t* __restrict__ Cvh, uint16_t* __restrict__ Cvl)
{
    extern __shared__ __align__(16) uint16_t dsm[];
    const int tid = threadIdx.x, lane = tid & 31, wid = tid >> 5;
    const int warp_m = wid >> 2, warp_n = wid & 3;
    const bool isS = (blockIdx.y < NSCALAR_BLOCKS);
    const size_t rowBase = (size_t)(isS ? blockIdx.y : blockIdx.y - NSCALAR_BLOCKS) * 128;
    const int colBase = blockIdx.x * 128;
    const float* A1 = isS ? A1s : A1v;
    const float* A2 = isS ? A2s : A2v;
    const uint16_t* Bh = isS ? Bhs : Bhv;
    const uint16_t* Bl = isS ? Bls : Blv;
    const float* bias = isS ? biass : nullptr;
    uint16_t* Ch = isS ? Csh : Cvh;
    uint16_t* Cl = isS ? Csl : Cvl;

    const int am = tid >> 1, ak = (tid & 1) * 8;
    const int bk = tid >> 4, bn = (tid & 15) * 8;

    const float* a1p = A1 + (rowBase + am) * H + ak;
    const float* a2p = A2 + (rowBase + am) * H + ak;
    const uint16_t* bhp = Bh + (size_t)bk * H + colBase + bn;
    const uint16_t* blp = Bl + (size_t)bk * H + colBase + bn;

    uint32_t sA0 = (uint32_t)__cvta_generic_to_shared(dsm);
    uint32_t sB0 = sA0 + 4 * ABUF_B;
    uint32_t bDst = sB0 + (uint32_t)((bk * BROW + bn) * 2);
    uint16_t* aStore = dsm + (am * AROW + ak);

    const int a_row0 = warp_m * 64 + (lane & 7) + ((lane >> 3) & 1) * 8;
    const int a_kgrp = lane >> 4;
    uint32_t aBase = sA0 + (uint32_t)((a_row0 * AROW + a_kgrp * 8) * 2);
    const int b_krow = (lane & 7) + ((lane >> 3) & 1) * 8;
    const int b_ngrp = lane >> 4;
    uint32_t bBase = sB0 + (uint32_t)((b_krow * BROW + warp_n * 32 + b_ngrp * 8) * 2);

    float acc[4][4][4];
#pragma unroll
    for (int i = 0; i < 4; i++)
#pragma unroll
        for (int j = 0; j < 4; j++)
#pragma unroll
            for (int q = 0; q < 4; q++) acc[i][j][q] = 0.f;

    cpa16(bDst, bhp);
    cpa16(bDst + B_PLANE_B, blp);
    cpa16(bDst + BBUF_B, bhp + (size_t)16 * H);
    cpa16(bDst + BBUF_B + B_PLANE_B, blp + (size_t)16 * H);
    cpa_commit();
    {
        float4 ax, ay;
        gloadA(a1p, a2p, 0, ax, ay);
        cvt_store8(aStore, aStore + A_HL, ax, ay);
        gloadA(a1p, a2p, 16, ax, ay);
        cvt_store8(aStore + ABUF_B / 2, aStore + ABUF_B / 2 + A_HL, ax, ay);
    }
    cpa_wait0();
    __syncthreads();

    const int NT = H / 16;
    for (int t = 0; t < NT; t += 2) {
        if (t + 2 < NT) {
            int c2 = t + 2, c3 = t + 3;
            size_t k2 = (size_t)c2 * 16, k3 = (size_t)c3 * 16;
            uint32_t bd2 = bDst + (uint32_t)((c2 & 3) * BBUF_B);
            uint32_t bd3 = bDst + (uint32_t)((c3 & 3) * BBUF_B);
            cpa16(bd2, bhp + k2 * H);
            cpa16(bd2 + B_PLANE_B, blp + k2 * H);
            cpa16(bd3, bhp + k3 * H);
            cpa16(bd3 + B_PLANE_B, blp + k3 * H);
            cpa_commit();
            float4 ax, ay;
            gloadA(a1p, a2p, (int)k2, ax, ay);
            cvt_store8(aStore + (c2 & 3) * (ABUF_B / 2),
                       aStore + (c2 & 3) * (ABUF_B / 2) + A_HL, ax, ay);
            gloadA(a1p, a2p, (int)k3, ax, ay);
            cvt_store8(aStore + (c3 & 3) * (ABUF_B / 2),
                       aStore + (c3 & 3) * (ABUF_B / 2) + A_HL, ax, ay);
        }
        mma_chunk(aBase + (uint32_t)((t & 3) * ABUF_B),
                  bBase + (uint32_t)((t & 3) * BBUF_B), acc);
        mma_chunk(aBase + (uint32_t)(((t + 1) & 3) * ABUF_B),
                  bBase + (uint32_t)(((t + 1) & 3) * BBUF_B), acc);
        if (t + 2 < NT) {
            cpa_wait0();
            __syncthreads();
        }
    }

#pragma unroll
    for (int mt = 0; mt < 4; mt++) {
        size_t r0 = rowBase + warp_m * 64 + mt * 16 + (lane >> 2);
#pragma unroll
        for (int nt = 0; nt < 4; nt++) {
            int col = colBase + warp_n * 32 + nt * 8 + (lane & 3) * 2;
            float v0 = acc[mt][nt][0], v1 = acc[mt][nt][1];
            float v2 = acc[mt][nt][2], v3 = acc[mt][nt][3];
            if (bias) {
                float2 bb = *(const float2*)&bias[col];
                v0 += bb.x; v1 += bb.y; v2 += bb.x; v3 += bb.y;
            }
            v0 = sspf(v0); v1 = sspf(v1); v2 = sspf(v2); v3 = sspf(v3);
            *(uint32_t*)&Ch[r0 * H + col]       = pk2(v0, v1);
            *(uint32_t*)&Cl[r0 * H + col]       = pk2(bres(v0), bres(v1));
            *(uint32_t*)&Ch[(r0 + 8) * H + col] = pk2(v2, v3);
            *(uint32_t*)&Cl[(r0 + 8) * H + col] = pk2(bres(v2), bres(v3));
        }
    }
}

// ---------------- layer-2 GEMM: bf16 planes in -> bf16 hi/lo planes out -----------
__global__ __launch_bounds__(256, 2)
void k_gemm2(const uint16_t* __restrict__ Ahs, const uint16_t* __restrict__ Als,
             const uint16_t* __restrict__ Ahv, const uint16_t* __restrict__ Alv,
             const uint16_t* __restrict__ Bhs, const uint16_t* __restrict__ Bls,
             const uint16_t* __restrict__ Bhv, const uint16_t* __restrict__ Blv,
             const float* __restrict__ biass,
             uint16_t* __restrict__ Csh, uint16_t* __restrict__ Csl,
             uint16_t* __restrict__ Cvh, uint16_t* __restrict__ Cvl)
{
    extern __shared__ __align__(16) uint16_t dsm[];
    const int tid = threadIdx.x, lane = tid & 31, wid = tid >> 5;
    const int warp_m = wid >> 2, warp_n = wid & 3;
    const bool isS = (blockIdx.y < NSCALAR_BLOCKS);
    const size_t rowBase = (size_t)(isS ? blockIdx.y : blockIdx.y - NSCALAR_BLOCKS) * 128;
    const int colBase = blockIdx.x * 128;
    const uint16_t* Ah = isS ? Ahs : Ahv;
    const uint16_t* Al = isS ? Als : Alv;
    const uint16_t* Bh = isS ? Bhs : Bhv;
    const uint16_t* Bl = isS ? Bls : Blv;
    const float* bias = isS ? biass : nullptr;
    uint16_t* Ch = isS ? Csh : Cvh;
    uint16_t* Cl = isS ? Csl : Cvl;

    const int am = tid >> 1, ak = (tid & 1) * 8;
    const int bk = tid >> 4, bn = (tid & 15) * 8;

    const uint16_t* ahp = Ah + (rowBase + am) * H + ak;
    const uint16_t* alp = Al + (rowBase + am) * H + ak;
    const uint16_t* bhp = Bh + (size_t)bk * H + colBase + bn;
    const uint16_t* blp = Bl + (size_t)bk * H + colBase + bn;

    uint32_t sA0 = (uint32_t)__cvta_generic_to_shared(dsm);
    uint32_t sB0 = sA0 + 4 * ABUF_B;
    uint32_t aDst = sA0 + (uint32_t)((am * AROW + ak) * 2);
    uint32_t bDst = sB0 + (uint32_t)((bk * BROW + bn) * 2);

    const int a_row0 = warp_m * 64 + (lane & 7) + ((lane >> 3) & 1) * 8;
    const int a_kgrp = lane >> 4;
    uint32_t aBase = sA0 + (uint32_t)((a_row0 * AROW + a_kgrp * 8) * 2);
    const int b_krow = (lane & 7) + ((lane >> 3) & 1) * 8;
    const int b_ngrp = lane >> 4;
    uint32_t bBase = sB0 + (uint32_t)((b_krow * BROW + warp_n * 32 + b_ngrp * 8) * 2);

    float acc[4][4][4];
#pragma unroll
    for (int i = 0; i < 4; i++)
#pragma unroll
        for (int j = 0; j < 4; j++)
#pragma unroll
            for (int q = 0; q < 4; q++) acc[i][j][q] = 0.f;

#pragma unroll
    for (int c = 0; c < 2; c++) {
        size_t k0 = (size_t)c * 16;
        uint32_t ad = aDst + (uint32_t)(c * ABUF_B);
        uint32_t bd = bDst + (uint32_t)(c * BBUF_B);
        cpa16(ad, ahp + k0);
        cpa16(ad + A_PLANE_B, alp + k0);
        cpa16(bd, bhp + k0 * H);
        cpa16(bd + B_PLANE_B, blp + k0 * H);
    }
    cpa_commit();
    cpa_wait0();
    __syncthreads();

    const int NT = H / 16;
    for (int t = 0; t < NT; t += 2) {
        if (t + 2 < NT) {
#pragma unroll
            for (int d = 2; d < 4; d++) {
                int c = t + d;
                size_t k0 = (size_t)c * 16;
                uint32_t ad = aDst + (uint32_t)((c & 3) * ABUF_B);
                uint32_t bd = bDst + (uint32_t)((c & 3) * BBUF_B);
                cpa16(ad, ahp + k0);
                cpa16(ad + A_PLANE_B, alp + k0);
                cpa16(bd, bhp + k0 * H);
                cpa16(bd + B_PLANE_B, blp + k0 * H);
            }
            cpa_commit();
        }
        mma_chunk(aBase + (uint32_t)((t & 3) * ABUF_B),
                  bBase + (uint32_t)((t & 3) * BBUF_B), acc);
        mma_chunk(aBase + (uint32_t)(((t + 1) & 3) * ABUF_B),
                  bBase + (uint32_t)(((t + 1) & 3) * BBUF_B), acc);
        if (t + 2 < NT) {
            cpa_wait0();
            __syncthreads();
        }
    }

#pragma unroll
    for (int mt = 0; mt < 4; mt++) {
        size_t r0 = rowBase + warp_m * 64 + mt * 16 + (lane >> 2);
#pragma unroll
        for (int nt = 0; nt < 4; nt++) {
            int col = colBase + warp_n * 32 + nt * 8 + (lane & 3) * 2;
            float v0 = acc[mt][nt][0], v1 = acc[mt][nt][1];
            float v2 = acc[mt][nt][2], v3 = acc[mt][nt][3];
            if (bias) {
                float2 bb = *(const float2*)&bias[col];
                v0 += bb.x; v1 += bb.y; v2 += bb.x; v3 += bb.y;
            }
            *(uint32_t*)&Ch[r0 * H + col]       = pk2(v0, v1);
            *(uint32_t*)&Cl[r0 * H + col]       = pk2(bres(v0), bres(v1));
            *(uint32_t*)&Ch[(r0 + 8) * H + col] = pk2(v2, v3);
            *(uint32_t*)&Cl[(r0 + 8) * H + col] = pk2(bres(v2), bres(v3));
        }
    }
}

// ---------------- per-fragment stats: 2-buffer 8-unit Gram pipeline --------------
// units = 4 features x 2 half-K (128 k each): HALF the wait/sync pairs of the
// 16-unit pipeline. Buffers 34.8KB each; 69.6KB total -> 2 CTAs/SM.
#define ZROW 136
#define ZPLANE (64 * ZROW)
#define FRAG_SMEM (2 * 2 * ZPLANE * 2)   // 69632 bytes

__global__ __launch_bounds__(256, 2)
void k_frag(float* __restrict__ out) {
    extern __shared__ __align__(16) uint16_t z[];
    __shared__ float sdiag[64];
    __shared__ float rd[48];
    __shared__ int s_last;
    int f = blockIdx.x, t = threadIdx.x;
    int cnt = g_counts[f], off = g_offsets[f];
    int wid = t >> 5, lane = t & 31;
    float serr = 0.f, derr = 0.f;
    float tr0 = 0.f, tr123 = 0.f, gs0 = 0.f, gs123 = 0.f;

    uint32_t z0 = (uint32_t)__cvta_generic_to_shared(z);

    if (cnt >= 2 && cnt <= MAXM) {
        const int Mt = (cnt + 15) >> 4;
        int tm[2] = {-1, -1}, tn[2] = {-1, -1};
        {
            int idx = 0;
            for (int mt = 0; mt < Mt; mt++)
                for (int nt = mt; nt < Mt; nt++) {
                    if ((idx & 7) == wid) {
                        int s = idx >> 3;
                        if (s < 2) { tm[s] = mt; tn[s] = nt; }
                    }
                    idx++;
                }
        }
        const int lrow = t >> 2;
        const int lkq = (t & 3) * 32;       // 32 halfwords = 64B segment per thread
        int lnd = (lrow < cnt) ? g_nodes[off + lrow] : -1;
        const int fr = (lane & 7) + ((lane >> 3) & 1) * 8;
        const int fk = (lane >> 4) * 8;
        const int sz = (lnd >= 0) ? 16 : 0;

        // unit u: feat = u>>1, k-half = (u&1)*128; buffer = u&1
        auto issue_unit = [&](int u) {
            int feat = u >> 1, kh = (u & 1) * 128;
            const uint16_t *sh, *slo;
            if (lnd >= 0) {
                if (feat == 0) {
                    sh = g_sih + (size_t)lnd * H; slo = g_sil + (size_t)lnd * H;
                } else {
                    sh  = g_vih + ((size_t)lnd * 3 + feat - 1) * H;
                    slo = g_vil + ((size_t)lnd * 3 + feat - 1) * H;
                }
            } else { sh = g_sih; slo = g_sil; }
            uint32_t dst = z0 + (uint32_t)(((u & 1) * 2 * ZPLANE + lrow * ZROW + lkq) * 2);
#pragma unroll
            for (int j = 0; j < 4; j++) {
                cpa16z(dst + j * 16, sh + kh + lkq + j * 8, sz);
                cpa16z(dst + ZPLANE * 2 + j * 16, slo + kh + lkq + j * 8, sz);
            }
            cpa_commit();
        };

        issue_unit(0);
        issue_unit(1);

        float acc[2][2][4];
        for (int u = 0; u < 8; u++) {
            if ((u & 1) == 0) {
#pragma unroll
                for (int a = 0; a < 2; a++)
#pragma unroll
                    for (int b = 0; b < 2; b++)
#pragma unroll
                        for (int q = 0; q < 4; q++) acc[a][b][q] = 0.f;
            }
            if (u < 7) asm volatile("cp.async.wait_group 1;" ::: "memory");
            else       asm volatile("cp.async.wait_group 0;" ::: "memory");
            __syncthreads();

            uint32_t zhb = z0 + (uint32_t)((u & 1) * 2 * ZPLANE * 2);
            uint32_t zlb = zhb + (uint32_t)(ZPLANE * 2);
#pragma unroll
            for (int ti = 0; ti < 2; ti++) {
                if (tm[ti] < 0) continue;
#pragma unroll
                for (int ks = 0; ks < 8; ks++) {
                    uint32_t aoff = (uint32_t)(((tm[ti] * 16 + fr) * ZROW + ks * 16 + fk) * 2);
                    uint32_t boff = (uint32_t)(((tn[ti] * 16 + fr) * ZROW + ks * 16 + fk) * 2);
                    uint32_t ah[4], al[4], bh[4], bl[4];
                    ldsm4(zhb + aoff, ah);
                    ldsm4(zlb + aoff, al);
                    ldsm4(zhb + boff, bh);
                    ldsm4(zlb + boff, bl);
                    mma16816(acc[ti][0], ah, bh[0], bh[2]);
                    mma16816(acc[ti][1], ah, bh[1], bh[3]);
                    mma16816(acc[ti][0], ah, bl[0], bl[2]);
                    mma16816(acc[ti][1], ah, bl[1], bl[3]);
                    mma16816(acc[ti][0], al, bh[0], bh[2]);
                    mma16816(acc[ti][1], al, bh[1], bh[3]);
                }
            }
            __syncthreads();
            if (u + 2 < 8) issue_unit(u + 2);

            if (u & 1) {
                int feat = u >> 1;
                // diagonal -> smem
                {
                    int r = lane >> 2, c = (lane & 3) * 2;
#pragma unroll
                    for (int ti = 0; ti < 2; ti++) {
                        if (tm[ti] < 0 || tm[ti] != tn[ti]) continue;
#pragma unroll
                        for (int hh = 0; hh < 2; hh++) {
                            int nl0 = hh * 8 + c;
                            if (r == nl0)     sdiag[tm[ti] * 16 + r]     = acc[ti][hh][0];
                            if (r == nl0 + 1) sdiag[tm[ti] * 16 + r]     = acc[ti][hh][1];
                            if (r + 8 == nl0)     sdiag[tm[ti] * 16 + r + 8] = acc[ti][hh][2];
                            if (r + 8 == nl0 + 1) sdiag[tm[ti] * 16 + r + 8] = acc[ti][hh][3];
                        }
                    }
                }
                __syncthreads();

                if (t < cnt) {
                    float d = sdiag[t];
                    if (feat == 0) tr0 += d; else tr123 += d;
                }

                {
                    float err = 0.f, gsum = 0.f;
                    int r = lane >> 2, c = (lane & 3) * 2;
#pragma unroll
                    for (int ti = 0; ti < 2; ti++) {
                        if (tm[ti] < 0) continue;
                        int mb = tm[ti] * 16, nb = tn[ti] * 16;
                        bool isDiag = (tm[ti] == tn[ti]);
#pragma unroll
                        for (int hh = 0; hh < 2; hh++) {
                            int n0 = nb + hh * 8 + c;
#pragma unroll
                            for (int q = 0; q < 4; q++) {
                                int m = mb + r + (q >> 1) * 8;
                                int n = n0 + (q & 1);
                                float v = acc[ti][hh][q];
                                if (!isDiag) {
                                    gsum += 2.f * v;
                                } else {
                                    if (m < n) gsum += 2.f * v;
                                    else if (m == n) gsum += v;
                                }
                                if (n < cnt && m < n) {
                                    float rs = rsqrtf(fmaxf(sdiag[m] * sdiag[n], 1e-24f));
                                    float e = fmaf(v, rs, -C_SIM);
                                    err = fmaf(e, e, err);
                                }
                            }
                        }
                    }
                    if (feat == 0) { serr = err; gs0 = gsum; }
                    else { derr += err; gs123 += gsum; }
                }
                __syncthreads();
            }
        }
    } else if (cnt > MAXM) {
        // fallback (never expected): gmem-direct from bf16 planes, exact two-pass
        float* mean = (float*)z;
        float as = 0.f, a0m = 0.f, a1m = 0.f, a2m = 0.f;
        for (int m = 0; m < cnt; m++) {
            int nd = g_nodes[off + m];
            as += b2f(g_sih[(size_t)nd * H + t]) + b2f(g_sil[(size_t)nd * H + t]);
            size_t vb = (size_t)nd * 3 * H;
            a0m += b2f(g_vih[vb + t]) + b2f(g_vil[vb + t]);
            a1m += b2f(g_vih[vb + H + t]) + b2f(g_vil[vb + H + t]);
            a2m += b2f(g_vih[vb + 2 * H + t]) + b2f(g_vil[vb + 2 * H + t]);
        }
        float invn = 1.f / (float)cnt;
        mean[t] = as * invn; mean[256 + t] = a0m * invn;
        mean[512 + t] = a1m * invn; mean[768 + t] = a2m * invn;
        __syncthreads();
        for (int m = 0; m < cnt; m++) {
            int nd = g_nodes[off + m];
            float d0 = b2f(g_sih[(size_t)nd * H + t]) + b2f(g_sil[(size_t)nd * H + t]) - mean[t];
            tr0 = fmaf(d0, d0, tr0);
            size_t vb = (size_t)nd * 3 * H;
            float d1 = b2f(g_vih[vb + t]) + b2f(g_vil[vb + t]) - mean[256 + t];
            float d2 = b2f(g_vih[vb + H + t]) + b2f(g_vil[vb + H + t]) - mean[512 + t];
            float d3 = b2f(g_vih[vb + 2 * H + t]) + b2f(g_vil[vb + 2 * H + t]) - mean[768 + t];
            tr123 = fmaf(d1, d1, tr123); tr123 = fmaf(d2, d2, tr123); tr123 = fmaf(d3, d3, tr123);
        }
        for (int feat = 0; feat < 4; feat++) {
            float acc = 0.f;
            for (int a = wid; a < cnt - 1; a += 8) {
                int na = g_nodes[off + a];
                const uint16_t* rah = (feat == 0) ? g_sih + (size_t)na * H
                                                  : g_vih + ((size_t)na * 3 + feat - 1) * H;
                const uint16_t* ral = (feat == 0) ? g_sil + (size_t)na * H
                                                  : g_vil + ((size_t)na * 3 + feat - 1) * H;
                for (int b = a + 1 + lane; b < cnt; b += 32) {
                    int nb = g_nodes[off + b];
                    const uint16_t* rbh = (feat == 0) ? g_sih + (size_t)nb * H
                                                      : g_vih + ((size_t)nb * 3 + feat - 1) * H;
                    const uint16_t* rbl = (feat == 0) ? g_sil + (size_t)nb * H
                                                      : g_vil + ((size_t)nb * 3 + feat - 1) * H;
                    float dot = 0.f, sa = 0.f, sb = 0.f;
                    for (int k = 0; k < H; k++) {
                        float x = b2f(rah[k]) + b2f(ral[k]);
                        float y = b2f(rbh[k]) + b2f(rbl[k]);
                        dot = fmaf(x, y, dot);
                        sa = fmaf(x, x, sa);
                        sb = fmaf(y, y, sb);
                    }
                    float e = dot / (fmaxf(sqrtf(sa), 1e-12f) * fmaxf(sqrtf(sb), 1e-12f)) - C_SIM;
                    acc = fmaf(e, e, acc);
                }
            }
            if (feat == 0) serr = acc; else derr += acc;
        }
    }

    for (int o = 16; o; o >>= 1) {
        tr0   += __shfl_xor_sync(0xffffffffu, tr0, o);
        tr123 += __shfl_xor_sync(0xffffffffu, tr123, o);
        gs0   += __shfl_xor_sync(0xffffffffu, gs0, o);
        gs123 += __shfl_xor_sync(0xffffffffu, gs123, o);
        serr  += __shfl_xor_sync(0xffffffffu, serr, o);
        derr  += __shfl_xor_sync(0xffffffffu, derr, o);
    }
    if (lane == 0) {
        rd[wid] = tr0; rd[8 + wid] = tr123; rd[16 + wid] = gs0;
        rd[24 + wid] = gs123; rd[32 + wid] = serr; rd[40 + wid] = derr;
    }
    __syncthreads();
    if (t == 0) {
        float a = 0.f, b = 0.f, c = 0.f, d = 0.f, e = 0.f, g = 0.f;
        for (int i = 0; i < 8; i++) {
            a += rd[i]; b += rd[8 + i]; c += rd[16 + i];
            d += rd[24 + i]; e += rd[32 + i]; g += rd[40 + i];
        }
        float invn = 1.f / (float)(cnt > 0 ? cnt : 1);
        g_svar[f] = a - c * invn;
        g_vvar[f] = b - d * invn;
        g_ssim[f] = e;
        g_dir[f]  = g;
        __threadfence();
        int old = atomicAdd(&g_done, 1);
        s_last = (old == NF - 1) ? 1 : 0;
    }
    __syncthreads();

    if (s_last) {
        __threadfence();
        float n  = (float)g_counts[t];
        float pc = n * (n - 1.f) * 0.5f;
        float ns  = fmaxf(n, 1.f);
        float pcs = fmaxf(pc, 1.f);
        float sl = g_svar[t] / ns + g_ssim[t] / pcs;
        float vl = g_vvar[t] / ns + g_dir[t] / (3.f * pcs);
        float fl = 0.5f * sl + 0.5f * vl;
        float val  = (pc > 0.f) ? fl : 0.f;
        float cntv = (pc > 0.f) ? 1.f : 0.f;
        for (int o = 16; o; o >>= 1) {
            val  += __shfl_xor_sync(0xffffffffu, val, o);
            cntv += __shfl_xor_sync(0xffffffffu, cntv, o);
        }
        __syncthreads();
        if (lane == 0) { rd[wid] = val; rd[8 + wid] = cntv; }
        __syncthreads();
        if (t == 0) {
            float tot = 0.f, tc = 0.f;
            for (int i = 0; i < 8; i++) { tot += rd[i]; tc += rd[8 + i]; }
            out[0] = (tc > 0.f) ? tot / fmaxf(tc, 1.f) : 0.f;
            g_done = 0;
        }
    }
}

// ---------------- launch ----------------
extern "C" void kernel_launch(void* const* d_in, const int* in_sizes, int n_in,
                              void* d_out, int out_size)
{
    const float* ss = (const float*)d_in[0];
    const float* sl = (const float*)d_in[1];
    const float* vs = (const float*)d_in[2];
    const float* vl = (const float*)d_in[3];
    const float* W1 = (const float*)d_in[4];
    const float* b1 = (const float*)d_in[5];
    const float* W2 = (const float*)d_in[6];
    const float* b2 = (const float*)d_in[7];
    const float* V1 = (const float*)d_in[8];
    const float* V2 = (const float*)d_in[9];
    const int*   frag = (const int*)d_in[10];
    float* out = (float*)d_out;

    void *pwh, *pwl, *ptsh, *ptsl, *ptvh, *ptvl, *psih, *psil, *pvih, *pvil;
    cudaGetSymbolAddress(&pwh, g_wh);
    cudaGetSymbolAddress(&pwl, g_wl);
    cudaGetSymbolAddress(&ptsh, g_tsh);
    cudaGetSymbolAddress(&ptsl, g_tsl);
    cudaGetSymbolAddress(&ptvh, g_tvh);
    cudaGetSymbolAddress(&ptvl, g_tvl);
    cudaGetSymbolAddress(&psih, g_sih);
    cudaGetSymbolAddress(&psil, g_sil);
    cudaGetSymbolAddress(&pvih, g_vih);
    cudaGetSymbolAddress(&pvil, g_vil);
    const uint16_t* wh = (const uint16_t*)pwh;
    const uint16_t* wl = (const uint16_t*)pwl;

    k_setup<<<257, 256>>>(frag, W1, W2, V1, V2);

    cudaFuncSetAttribute(k_gemm1, cudaFuncAttributeMaxDynamicSharedMemorySize, G_SMEM);
    cudaFuncSetAttribute(k_gemm2, cudaFuncAttributeMaxDynamicSharedMemorySize, G_SMEM);
    cudaFuncSetAttribute(k_frag, cudaFuncAttributeMaxDynamicSharedMemorySize, FRAG_SMEM);

    dim3 g(2, NSCALAR_BLOCKS + 192);
    k_gemm1<<<g, 256, G_SMEM>>>(ss, sl, vs, vl,
                                wh + 0 * 65536, wl + 0 * 65536,
                                wh + 2 * 65536, wl + 2 * 65536,
                                b1,
                                (uint16_t*)ptsh, (uint16_t*)ptsl,
                                (uint16_t*)ptvh, (uint16_t*)ptvl);
    k_gemm2<<<g, 256, G_SMEM>>>((uint16_t*)ptsh, (uint16_t*)ptsl,
                                (uint16_t*)ptvh, (uint16_t*)ptvl,
                                wh + 1 * 65536, wl + 1 * 65536,
                                wh + 3 * 65536, wl + 3 * 65536,
                                b2,
                                (uint16_t*)psih, (uint16_t*)psil,
                                (uint16_t*)pvih, (uint16_t*)pvil);

    k_frag<<<NF, 256, FRAG_SMEM>>>(out);
}